// round 5
// baseline (speedup 1.0000x reference)
#include <cuda_runtime.h>
#include <cuda_bf16.h>
#include <cstdint>

#define N_NODES 50000
#define MAX_E   800000
#define MAX_TOT (MAX_E + N_NODES)
#define F1 128
#define F2 64

// ---------------- scratch (no allocations allowed) ----------------
__device__ int   g_cnt[N_NODES];
__device__ int   g_cursor[N_NODES];
__device__ int   g_rowptr[N_NODES + 1];
__device__ int2  g_colnrm[MAX_TOT];      // .x = src col, .y = bitcast(norm)
__device__ float g_dinv[N_NODES];
__device__ float g_H1[(size_t)N_NODES * F1];   // x @ W1
__device__ float g_A1[(size_t)N_NODES * F1];   // relu(agg + b1)
__device__ float g_H2[(size_t)N_NODES * F2];   // A1 @ W2
__device__ int   g_is64;

#define CP_ASYNC16(dst, src) asm volatile("cp.async.ca.shared.global [%0], [%1], 16;" :: "r"(dst), "l"(src) : "memory")
#define CP_COMMIT()          asm volatile("cp.async.commit_group;" ::: "memory")
#define CP_WAIT(N)           asm volatile("cp.async.wait_group %0;" :: "n"(N) : "memory")

// ---------------- edge dtype probe + init ----------------
__global__ void k_init_detect(const void* ei) {
    int i = blockIdx.x * blockDim.x + threadIdx.x;
    if (i < N_NODES) { g_cnt[i] = 1; g_cursor[i] = 0; }
    if (i == 0) {
        const long long* p = (const long long*)ei;
        int ok = 1;
        for (int j = 0; j < 64; j++) {
            long long v = p[j];
            if (v < 0 || v >= N_NODES) { ok = 0; break; }
        }
        g_is64 = ok;
    }
}

__device__ __forceinline__ int edge_at(const void* ei, int E, int which, int idx) {
    if (g_is64) return (int)((const long long*)ei)[(size_t)which * E + idx];
    return ((const int*)ei)[(size_t)which * E + idx];
}

__global__ void k_degree(const void* __restrict__ ei, int E) {
    int e = blockIdx.x * blockDim.x + threadIdx.x;
    if (e < E) atomicAdd(&g_cnt[edge_at(ei, E, 1, e)], 1);
}

// ---------------- exclusive scan + dinv (single block) ----------------
__global__ void k_scan() {
    const int T = 1024;
    int t = threadIdx.x;
    const int per = (N_NODES + T - 1) / T;
    int s = t * per;
    int e = min(s + per, N_NODES);
    int local = 0;
    for (int i = s; i < e; i++) local += g_cnt[i];
    __shared__ int sm[T];
    sm[t] = local;
    __syncthreads();
    for (int off = 1; off < T; off <<= 1) {
        int v = (t >= off) ? sm[t - off] : 0;
        __syncthreads();
        sm[t] += v;
        __syncthreads();
    }
    int run = sm[t] - local;
    for (int i = s; i < e; i++) {
        int c = g_cnt[i];
        g_rowptr[i] = run;
        run += c;
        g_dinv[i] = rsqrtf((float)c);
    }
    if (t == T - 1) g_rowptr[N_NODES] = sm[T - 1];
}

// ---------------- CSR scatter (edges + self loops), packed 8B stores ----------------
__global__ void k_scatter(const void* __restrict__ ei, int E) {
    int i = blockIdx.x * blockDim.x + threadIdx.x;
    int tot = E + N_NODES;
    if (i >= tot) return;
    int s, d;
    if (i < E) { s = edge_at(ei, E, 0, i); d = edge_at(ei, E, 1, i); }
    else       { s = d = i - E; }
    int pos = g_rowptr[d] + atomicAdd(&g_cursor[d], 1);
    int2 v;
    v.x = s;
    v.y = __float_as_int(g_dinv[s] * g_dinv[d]);
    g_colnrm[pos] = v;
}

// ============ FFMA SGEMM: C[M,NOUT] = A[M,128] @ W[128,NOUT] ============
// 128 x NOUT x 16 CTA tile, 256 threads, 8x(8|4) thread tile,
// cp.async 2-stage for B, register-staged double buffer for A.
template<int NOUT>
__global__ __launch_bounds__(256, 2) void k_sgemm(const float* __restrict__ A,
        const float* __restrict__ W, float* __restrict__ C, int M) {
    constexpr int BN = (NOUT == 128) ? 8 : 4;
    __shared__ float As[2][16 * 128];
    __shared__ float Bs[2][16 * NOUT];

    const int tid = threadIdx.x;
    const int tx = tid & 15, ty = tid >> 4;
    const int rowBase = blockIdx.x * 128;

    // A loader: 2 float4 per stage (rows aRow, aRow+64; k = aK..aK+3)
    const int aRow = tid >> 2;
    const int aK   = (tid & 3) << 2;
    const float* aP0 = A + (size_t)(rowBase + aRow) * 128 + aK;
    const float* aP1 = aP0 + 64 * 128;
    const bool av0 = (rowBase + aRow) < M;
    const bool av1 = (rowBase + aRow + 64) < M;

    // B loader (cp.async)
    int bK, bN;
    if (NOUT == 128) { bK = tid >> 5; bN = (tid & 31) << 2; }
    else             { bK = tid >> 4; bN = (tid & 15) << 2; }
    const float* wP = W + bK * NOUT + bN;
    uint32_t bsm0 = (uint32_t)__cvta_generic_to_shared(&Bs[0][bK * NOUT + bN]);
    uint32_t bsm1 = (uint32_t)__cvta_generic_to_shared(&Bs[1][bK * NOUT + bN]);

    const float4 fz = make_float4(0.f, 0.f, 0.f, 0.f);
    float4 ra0, ra1;

    // ---- prologue: stage 0 ----
    ra0 = av0 ? *(const float4*)aP0 : fz;
    ra1 = av1 ? *(const float4*)aP1 : fz;
    CP_ASYNC16(bsm0, wP);
    if (NOUT == 128) CP_ASYNC16(bsm0 + 8 * NOUT * 4, wP + 8 * NOUT);
    CP_COMMIT();
    {
        float* as = As[0];
        as[(aK + 0) * 128 + aRow] = ra0.x;
        as[(aK + 1) * 128 + aRow] = ra0.y;
        as[(aK + 2) * 128 + aRow] = ra0.z;
        as[(aK + 3) * 128 + aRow] = ra0.w;
        as[(aK + 0) * 128 + aRow + 64] = ra1.x;
        as[(aK + 1) * 128 + aRow + 64] = ra1.y;
        as[(aK + 2) * 128 + aRow + 64] = ra1.z;
        as[(aK + 3) * 128 + aRow + 64] = ra1.w;
    }

    float acc[8][BN];
#pragma unroll
    for (int i = 0; i < 8; i++)
#pragma unroll
        for (int j = 0; j < BN; j++) acc[i][j] = 0.f;

#pragma unroll
    for (int t = 0; t < 8; t++) {
        const int buf = t & 1;
        if (t < 7) {
            ra0 = av0 ? *(const float4*)(aP0 + (t + 1) * 16) : fz;
            ra1 = av1 ? *(const float4*)(aP1 + (t + 1) * 16) : fz;
            uint32_t bdst = buf ? bsm0 : bsm1;
            const float* wsrc = wP + (size_t)(t + 1) * 16 * NOUT;
            CP_ASYNC16(bdst, wsrc);
            if (NOUT == 128) CP_ASYNC16(bdst + 8 * NOUT * 4, wsrc + 8 * NOUT);
            CP_COMMIT();
            CP_WAIT(1);
        } else {
            CP_WAIT(0);
        }
        __syncthreads();

        const float* as = As[buf];
        const float* bs = Bs[buf];
#pragma unroll
        for (int k = 0; k < 16; k++) {
            float4 a0 = *(const float4*)(as + k * 128 + ty * 4);
            float4 a1 = *(const float4*)(as + k * 128 + ty * 4 + 64);
            float4 b0 = *(const float4*)(bs + k * NOUT + tx * 4);
            float av[8] = {a0.x, a0.y, a0.z, a0.w, a1.x, a1.y, a1.z, a1.w};
            float bv[BN];
            bv[0] = b0.x; bv[1] = b0.y; bv[2] = b0.z; bv[3] = b0.w;
            if (NOUT == 128) {
                float4 b1 = *(const float4*)(bs + k * NOUT + tx * 4 + 64);
                bv[4] = b1.x; bv[5] = b1.y; bv[6] = b1.z; bv[7] = b1.w;
            }
#pragma unroll
            for (int i = 0; i < 8; i++)
#pragma unroll
                for (int j = 0; j < BN; j++)
                    acc[i][j] = fmaf(av[i], bv[j], acc[i][j]);
        }
        __syncthreads();

        if (t < 7) {
            float* asn = As[buf ^ 1];
            asn[(aK + 0) * 128 + aRow] = ra0.x;
            asn[(aK + 1) * 128 + aRow] = ra0.y;
            asn[(aK + 2) * 128 + aRow] = ra0.z;
            asn[(aK + 3) * 128 + aRow] = ra0.w;
            asn[(aK + 0) * 128 + aRow + 64] = ra1.x;
            asn[(aK + 1) * 128 + aRow + 64] = ra1.y;
            asn[(aK + 2) * 128 + aRow + 64] = ra1.z;
            asn[(aK + 3) * 128 + aRow + 64] = ra1.w;
        }
    }

    // ---- epilogue ----
#pragma unroll
    for (int i = 0; i < 8; i++) {
        int r = rowBase + ((i < 4) ? (ty * 4 + i) : (64 + ty * 4 + i - 4));
        if (r < M) {
            float* cr = C + (size_t)r * NOUT + tx * 4;
            *(float4*)cr = make_float4(acc[i][0], acc[i][1], acc[i][2], acc[i][3]);
            if (NOUT == 128)
                *(float4*)(cr + 64) = make_float4(acc[i][4], acc[i][5], acc[i][6], acc[i][7]);
        }
    }
}

// ---------------- layer-1 aggregation + bias + relu ----------------
__global__ __launch_bounds__(256) void k_agg1(const float* __restrict__ b1) {
    int warp = (blockIdx.x * blockDim.x + threadIdx.x) >> 5;
    if (warp >= N_NODES) return;
    int lane = threadIdx.x & 31;
    int beg = g_rowptr[warp], end = g_rowptr[warp + 1];
    const int off = lane << 2;
    float4 acc = make_float4(0.f, 0.f, 0.f, 0.f);
    int j = beg;
    for (; j + 4 <= end; j += 4) {
        int2 e0 = g_colnrm[j], e1 = g_colnrm[j + 1];
        int2 e2 = g_colnrm[j + 2], e3 = g_colnrm[j + 3];
        float4 h0 = *(const float4*)(g_H1 + (size_t)e0.x * F1 + off);
        float4 h1 = *(const float4*)(g_H1 + (size_t)e1.x * F1 + off);
        float4 h2 = *(const float4*)(g_H1 + (size_t)e2.x * F1 + off);
        float4 h3 = *(const float4*)(g_H1 + (size_t)e3.x * F1 + off);
        float w0 = __int_as_float(e0.y), w1 = __int_as_float(e1.y);
        float w2 = __int_as_float(e2.y), w3 = __int_as_float(e3.y);
        acc.x = fmaf(h0.x, w0, fmaf(h1.x, w1, fmaf(h2.x, w2, fmaf(h3.x, w3, acc.x))));
        acc.y = fmaf(h0.y, w0, fmaf(h1.y, w1, fmaf(h2.y, w2, fmaf(h3.y, w3, acc.y))));
        acc.z = fmaf(h0.z, w0, fmaf(h1.z, w1, fmaf(h2.z, w2, fmaf(h3.z, w3, acc.z))));
        acc.w = fmaf(h0.w, w0, fmaf(h1.w, w1, fmaf(h2.w, w2, fmaf(h3.w, w3, acc.w))));
    }
    for (; j < end; j++) {
        int2 e0 = g_colnrm[j];
        float w0 = __int_as_float(e0.y);
        float4 h0 = *(const float4*)(g_H1 + (size_t)e0.x * F1 + off);
        acc.x = fmaf(h0.x, w0, acc.x);
        acc.y = fmaf(h0.y, w0, acc.y);
        acc.z = fmaf(h0.z, w0, acc.z);
        acc.w = fmaf(h0.w, w0, acc.w);
    }
    float4 bb = *(const float4*)(b1 + off);
    float4 o;
    o.x = fmaxf(acc.x + bb.x, 0.f);
    o.y = fmaxf(acc.y + bb.y, 0.f);
    o.z = fmaxf(acc.z + bb.z, 0.f);
    o.w = fmaxf(acc.w + bb.w, 0.f);
    *(float4*)(g_A1 + (size_t)warp * F1 + off) = o;
}

// ---------------- layer-2 aggregation + bias + softmax ----------------
__global__ __launch_bounds__(256) void k_agg2(const float* __restrict__ b2,
                                              float* __restrict__ out) {
    int warp = (blockIdx.x * blockDim.x + threadIdx.x) >> 5;
    if (warp >= N_NODES) return;
    int lane = threadIdx.x & 31;
    int beg = g_rowptr[warp], end = g_rowptr[warp + 1];
    const int off = lane << 1;
    float2 acc = make_float2(0.f, 0.f);
    int j = beg;
    for (; j + 4 <= end; j += 4) {
        int2 e0 = g_colnrm[j], e1 = g_colnrm[j + 1];
        int2 e2 = g_colnrm[j + 2], e3 = g_colnrm[j + 3];
        float2 h0 = *(const float2*)(g_H2 + (size_t)e0.x * F2 + off);
        float2 h1 = *(const float2*)(g_H2 + (size_t)e1.x * F2 + off);
        float2 h2 = *(const float2*)(g_H2 + (size_t)e2.x * F2 + off);
        float2 h3 = *(const float2*)(g_H2 + (size_t)e3.x * F2 + off);
        float w0 = __int_as_float(e0.y), w1 = __int_as_float(e1.y);
        float w2 = __int_as_float(e2.y), w3 = __int_as_float(e3.y);
        acc.x = fmaf(h0.x, w0, fmaf(h1.x, w1, fmaf(h2.x, w2, fmaf(h3.x, w3, acc.x))));
        acc.y = fmaf(h0.y, w0, fmaf(h1.y, w1, fmaf(h2.y, w2, fmaf(h3.y, w3, acc.y))));
    }
    for (; j < end; j++) {
        int2 e0 = g_colnrm[j];
        float w0 = __int_as_float(e0.y);
        float2 h0 = *(const float2*)(g_H2 + (size_t)e0.x * F2 + off);
        acc.x = fmaf(h0.x, w0, acc.x);
        acc.y = fmaf(h0.y, w0, acc.y);
    }
    float2 bb = *(const float2*)(b2 + off);
    float l0 = acc.x + bb.x;
    float l1 = acc.y + bb.y;
    float m = fmaxf(l0, l1);
#pragma unroll
    for (int o = 16; o > 0; o >>= 1)
        m = fmaxf(m, __shfl_xor_sync(0xffffffffu, m, o));
    float e0 = __expf(l0 - m);
    float e1 = __expf(l1 - m);
    float s = e0 + e1;
#pragma unroll
    for (int o = 16; o > 0; o >>= 1)
        s += __shfl_xor_sync(0xffffffffu, s, o);
    float inv = 1.0f / s;
    *(float2*)(out + (size_t)warp * F2 + off) = make_float2(e0 * inv, e1 * inv);
}

// ---------------- launch ----------------
extern "C" void kernel_launch(void* const* d_in, const int* in_sizes, int n_in,
                              void* d_out, int out_size) {
    const float* x  = (const float*)d_in[0];
    const void*  ei = d_in[1];
    const float* W1 = (const float*)d_in[2];
    const float* b1 = (const float*)d_in[3];
    const float* W2 = (const float*)d_in[4];
    const float* b2 = (const float*)d_in[5];
    float* out = (float*)d_out;
    int E = in_sizes[1] / 2;

    float *H1, *A1, *H2;
    cudaGetSymbolAddress((void**)&H1, g_H1);
    cudaGetSymbolAddress((void**)&A1, g_A1);
    cudaGetSymbolAddress((void**)&H2, g_H2);

    const int nTiles = (N_NODES + 127) / 128;   // 391

    k_init_detect<<<(N_NODES + 255) / 256, 256>>>(ei);
    k_degree<<<(E + 255) / 256, 256>>>(ei, E);
    k_scan<<<1, 1024>>>();
    k_scatter<<<(E + N_NODES + 255) / 256, 256>>>(ei, E);

    k_sgemm<128><<<nTiles, 256>>>(x, W1, H1, N_NODES);
    k_agg1<<<(N_NODES * 32 + 255) / 256, 256>>>(b1);
    k_sgemm<64><<<nTiles, 256>>>(A1, W2, H2, N_NODES);
    k_agg2<<<(N_NODES * 32 + 255) / 256, 256>>>(b2, out);
}